// round 8
// baseline (speedup 1.0000x reference)
#include <cuda_runtime.h>
#include <cuda_bf16.h>
#include <math.h>

// ---------------------------------------------------------------------------
// GPT-2 forward (B=2, S=1024, D=768, H=12, L=12, vocab=50257), fp32.
// Round 7: round-6 design with BK=16 slabs in all GEMM mainloops — barrier
// count halved again and 2x LDG batch per slab (4 back-to-back LDG.128 per
// thread), 1024 FFMA-cycles of cover per slab.
// ---------------------------------------------------------------------------

#define B_   2
#define S_   1024
#define T_   (B_ * S_)        // 2048 tokens
#define D_   768
#define H_   12
#define HD_  64
#define DFF_ 3072
#define L_   12
#define V_   50257
#define ATT_SCALE 0.125f      // 1/sqrt(64)
#define NSPLIT 3
#define NQB  (S_ / 128)       // q-blocks per (b,h) = 8

// Scratch (device globals — no allocation allowed)
__device__ float g_h[T_ * D_];            // residual stream
__device__ float g_a[T_ * D_];            // LN output
__device__ float g_qkv[T_ * 3 * D_];      // qkv
__device__ float g_att[T_ * D_];          // attention output
__device__ float g_ff[T_ * DFF_];         // FFN hidden
__device__ float g_part[NSPLIT * T_ * D_];// split-K partials (narrow GEMMs)

// ---------------------------------------------------------------------------
// LayerNorm: one block (256 threads) per token row of 768.
// ---------------------------------------------------------------------------
__global__ void ln_kernel(const float* __restrict__ x,
                          const float* __restrict__ g,
                          const float* __restrict__ b,
                          float* __restrict__ y) {
    int row = blockIdx.x;
    const float* xr = x + (size_t)row * D_;
    int t = threadIdx.x;

    float a0 = xr[t], a1 = xr[t + 256], a2 = xr[t + 512];
    float s = a0 + a1 + a2;

    __shared__ float sh[8];
    #pragma unroll
    for (int o = 16; o; o >>= 1) s += __shfl_xor_sync(0xffffffffu, s, o);
    if ((t & 31) == 0) sh[t >> 5] = s;
    __syncthreads();
    float tot = 0.f;
    #pragma unroll
    for (int i = 0; i < 8; i++) tot += sh[i];
    float mean = tot * (1.0f / 768.0f);

    float d0 = a0 - mean, d1 = a1 - mean, d2 = a2 - mean;
    float vs = d0 * d0 + d1 * d1 + d2 * d2;
    __syncthreads();
    #pragma unroll
    for (int o = 16; o; o >>= 1) vs += __shfl_xor_sync(0xffffffffu, vs, o);
    if ((t & 31) == 0) sh[t >> 5] = vs;
    __syncthreads();
    float vtot = 0.f;
    #pragma unroll
    for (int i = 0; i < 8; i++) vtot += sh[i];
    float inv = rsqrtf(vtot * (1.0f / 768.0f) + 1e-5f);

    float* yr = y + (size_t)row * D_;
    yr[t]       = d0 * inv * g[t]       + b[t];
    yr[t + 256] = d1 * inv * g[t + 256] + b[t + 256];
    yr[t + 512] = d2 * inv * g[t + 512] + b[t + 512];
}

// ---------------------------------------------------------------------------
// Tiled causal attention.
// Block = 128 threads (4 warps) = 128 queries of one (b,h). Lane owns one
// query: q[64] and acc[64] in registers, private online softmax (no shfl).
// K/V staged in 32-key smem tiles, read as broadcast LDS.
// ---------------------------------------------------------------------------
__global__ __launch_bounds__(128) void attn_kernel(
    const float* __restrict__ qkv, float* __restrict__ out) {
    __shared__ __align__(16) float Ks[32][64];
    __shared__ __align__(16) float Vs[32][64];

    int bh   = blockIdx.x / NQB;
    int qblk = (NQB - 1) - (blockIdx.x % NQB);   // long blocks first
    int h = bh % H_;
    int b = bh / H_;
    int wid  = threadIdx.x >> 5;
    int lane = threadIdx.x & 31;

    int qg = qblk * 128 + wid * 32 + lane;       // this lane's query
    const float* base = qkv + (size_t)b * S_ * (3 * D_);

    // load q (scaled) into registers
    float qr[64];
    const float4* qp = (const float4*)(base + (size_t)qg * (3 * D_) + h * HD_);
    #pragma unroll
    for (int d4 = 0; d4 < 16; d4++) {
        float4 v = qp[d4];
        qr[4 * d4 + 0] = v.x * ATT_SCALE;
        qr[4 * d4 + 1] = v.y * ATT_SCALE;
        qr[4 * d4 + 2] = v.z * ATT_SCALE;
        qr[4 * d4 + 3] = v.w * ATT_SCALE;
    }

    float m = -1e30f, l = 0.f;
    float acc[64];
    #pragma unroll
    for (int d = 0; d < 64; d++) acc[d] = 0.f;

    int my_tiles    = qblk * 4 + wid + 1;        // tiles this warp needs
    int block_tiles = qblk * 4 + 4;              // tiles the block stages

    for (int t = 0; t < block_tiles; t++) {
        int jbase = t * 32;
        // cooperative K/V tile load: 512 float4 slots each, 128 threads x 4
        #pragma unroll
        for (int u = 0; u < 4; u++) {
            int slot = threadIdx.x + u * 128;    // 0..511
            int jr = slot >> 4;                  // key row 0..31
            int c4 = slot & 15;                  // float4 col 0..15
            const float* rowp = base + (size_t)(jbase + jr) * (3 * D_) + h * HD_ + c4 * 4;
            *(float4*)(&Ks[jr][c4 * 4]) = *(const float4*)(rowp + D_);
            *(float4*)(&Vs[jr][c4 * 4]) = *(const float4*)(rowp + 2 * D_);
        }
        __syncthreads();

        if (t < my_tiles) {
            // pass 1: 32 scores (4 interleaved partials for ILP)
            float s[32];
            float tmax = -1e30f;
            #pragma unroll
            for (int j = 0; j < 32; j++) {
                float s0 = 0.f, s1 = 0.f, s2 = 0.f, s3 = 0.f;
                #pragma unroll
                for (int d4 = 0; d4 < 16; d4++) {
                    float4 kv = *(const float4*)(&Ks[j][d4 * 4]);
                    s0 += qr[4 * d4 + 0] * kv.x;
                    s1 += qr[4 * d4 + 1] * kv.y;
                    s2 += qr[4 * d4 + 2] * kv.z;
                    s3 += qr[4 * d4 + 3] * kv.w;
                }
                float sv = (s0 + s1) + (s2 + s3);
                if (jbase + j > qg) sv = -1e30f;  // causal mask
                s[j] = sv;
                tmax = fmaxf(tmax, sv);
            }
            // merge running max, rescale state
            float mn = fmaxf(m, tmax);
            float c  = __expf(m - mn);
            l *= c;
            #pragma unroll
            for (int d = 0; d < 64; d++) acc[d] *= c;
            // pass 2: weight V
            #pragma unroll
            for (int j = 0; j < 32; j++) {
                float p = __expf(s[j] - mn);
                l += p;
                #pragma unroll
                for (int d4 = 0; d4 < 16; d4++) {
                    float4 vv = *(const float4*)(&Vs[j][d4 * 4]);
                    acc[4 * d4 + 0] += p * vv.x;
                    acc[4 * d4 + 1] += p * vv.y;
                    acc[4 * d4 + 2] += p * vv.z;
                    acc[4 * d4 + 3] += p * vv.w;
                }
            }
            m = mn;
        }
        __syncthreads();
    }

    float invl = 1.0f / l;
    float4* op = (float4*)(out + (size_t)(b * S_ + qg) * D_ + h * HD_);
    #pragma unroll
    for (int d4 = 0; d4 < 16; d4++) {
        float4 r;
        r.x = acc[4 * d4 + 0] * invl;
        r.y = acc[4 * d4 + 1] * invl;
        r.z = acc[4 * d4 + 2] * invl;
        r.w = acc[4 * d4 + 3] * invl;
        op[d4] = r;
    }
}

// ---------------------------------------------------------------------------
// GEMM building blocks. BK=16 slabs, 2-stage ping-pong, 128x128 CTA tile,
// 8x8 thread tile, 256 threads.
// Per-thread slab loads: A: 2 float4 (row aRow, cols aCol..aCol+7)
//                        B: 2 float4 (row bRow, cols bCol..bCol+7)
// ---------------------------------------------------------------------------
#define GEMM_FRAG_STEP(ASRC, BSRC)                                          \
    {                                                                       \
        float4 rm0 = *(const float4*)(&ASRC[kk][tRow * 8]);                 \
        float4 rm1 = *(const float4*)(&ASRC[kk][tRow * 8 + 4]);             \
        float4 rn0 = *(const float4*)(&BSRC[kk][tCol * 8]);                 \
        float4 rn1 = *(const float4*)(&BSRC[kk][tCol * 8 + 4]);             \
        float rm[8] = {rm0.x, rm0.y, rm0.z, rm0.w,                          \
                       rm1.x, rm1.y, rm1.z, rm1.w};                         \
        float rn[8] = {rn0.x, rn0.y, rn0.z, rn0.w,                          \
                       rn1.x, rn1.y, rn1.z, rn1.w};                         \
        _Pragma("unroll")                                                   \
        for (int i = 0; i < 8; i++)                                         \
            _Pragma("unroll")                                               \
            for (int j = 0; j < 8; j++) acc[i][j] += rm[i] * rn[j];         \
    }

// A slab LDG: row aRow (0..127), k-cols aCol..aCol+7 (aCol = (tid&1)*8)
#define GEMM_LDG_NN(koff)                                                   \
    {                                                                       \
        av0 = *(const float4*)(Ap + (koff));                                \
        av1 = *(const float4*)(Ap + (koff) + 4);                            \
        bv0 = *(const float4*)(Bp + (size_t)(koff) * N);                    \
        bv1 = *(const float4*)(Bp + (size_t)((koff) + 8) * N);              \
    }

// STS into buffer q: A transposed scalar x8; B row bRow (first 8 rows get
// bv0's row, rows 8..15 get bv1's row) vectorized.
#define GEMM_STS_NN(q)                                                      \
    {                                                                       \
        As[q][aCol + 0][aRow] = av0.x;                                      \
        As[q][aCol + 1][aRow] = av0.y;                                      \
        As[q][aCol + 2][aRow] = av0.z;                                      \
        As[q][aCol + 3][aRow] = av0.w;                                      \
        As[q][aCol + 4][aRow] = av1.x;                                      \
        As[q][aCol + 5][aRow] = av1.y;                                      \
        As[q][aCol + 6][aRow] = av1.z;                                      \
        As[q][aCol + 7][aRow] = av1.w;                                      \
        *(float4*)(&Bs[q][bRow][bCol])     = bv0;                           \
        *(float4*)(&Bs[q][bRow + 8][bCol]) = bv1;                           \
    }

// ---------------------------------------------------------------------------
// SGEMM NN: C[M,N] = A[M,K] @ B[K,N] + bias (+ residual) (+ gelu)
// ---------------------------------------------------------------------------
__device__ __forceinline__ float gelu_erf(float x) {
    return 0.5f * x * (1.0f + erff(x * 0.70710678118654752f));
}

__global__ __launch_bounds__(256) void sgemm_nn(
    int M, int N, int K,
    const float* __restrict__ A, const float* __restrict__ Bm,
    const float* __restrict__ bias, const float* __restrict__ res,
    float* __restrict__ C, int act) {
    __shared__ __align__(16) float As[2][16][128];
    __shared__ __align__(16) float Bs[2][16][132];

    int tid  = threadIdx.x;
    int cRow = blockIdx.y, cCol = blockIdx.x;
    int tCol = tid & 15;
    int tRow = tid >> 4;

    int aRow = tid >> 1;          // 0..127
    int aCol = (tid & 1) * 8;     // 0 or 8
    int bRow = tid >> 5;          // 0..7  (+8 for second vec)
    int bCol = (tid & 31) * 4;    // 0..124

    const float* Ap = A + (size_t)cRow * 128 * K + (size_t)aRow * K + aCol;
    const float* Bp = Bm + cCol * 128 + (size_t)bRow * N + bCol;

    float acc[8][8];
    #pragma unroll
    for (int i = 0; i < 8; i++)
        #pragma unroll
        for (int j = 0; j < 8; j++) acc[i][j] = 0.f;

    float4 av0, av1, bv0, bv1;
    GEMM_LDG_NN(0)
    GEMM_STS_NN(0)
    __syncthreads();

    int p = 0;
    for (int k0 = 0; k0 < K; k0 += 16) {
        bool hasNext = (k0 + 16 < K);
        if (hasNext) GEMM_LDG_NN(k0 + 16)
        #pragma unroll
        for (int kk = 0; kk < 16; kk++) GEMM_FRAG_STEP(As[p], Bs[p])
        if (hasNext) {
            GEMM_STS_NN(p ^ 1)
            __syncthreads();
            p ^= 1;
        }
    }

    #pragma unroll
    for (int i = 0; i < 8; i++) {
        int gr = cRow * 128 + tRow * 8 + i;
        #pragma unroll
        for (int j = 0; j < 8; j++) {
            int gc = cCol * 128 + tCol * 8 + j;
            float v = acc[i][j] + bias[gc];
            if (act == 1) v = gelu_erf(v);
            if (res) v += res[(size_t)gr * N + gc];
            C[(size_t)gr * N + gc] = v;
        }
    }
}

// ---------------------------------------------------------------------------
// Split-K SGEMM NN: P[z][M,N] = A slab @ B slab. Partials only.
// ---------------------------------------------------------------------------
__global__ __launch_bounds__(256) void sgemm_nn_splitk(
    int M, int N, int K, int kLen,
    const float* __restrict__ A, const float* __restrict__ Bm,
    float* __restrict__ P) {
    __shared__ __align__(16) float As[2][16][128];
    __shared__ __align__(16) float Bs[2][16][132];

    int tid  = threadIdx.x;
    int cRow = blockIdx.y, cCol = blockIdx.x;
    int kOff = blockIdx.z * kLen;
    int tCol = tid & 15;
    int tRow = tid >> 4;

    int aRow = tid >> 1;
    int aCol = (tid & 1) * 8;
    int bRow = tid >> 5;
    int bCol = (tid & 31) * 4;

    const float* Ap = A + (size_t)cRow * 128 * K + (size_t)aRow * K + kOff + aCol;
    const float* Bp = Bm + cCol * 128 + (size_t)(kOff + bRow) * N + bCol;
    float* Cp = P + (size_t)blockIdx.z * M * N;

    float acc[8][8];
    #pragma unroll
    for (int i = 0; i < 8; i++)
        #pragma unroll
        for (int j = 0; j < 8; j++) acc[i][j] = 0.f;

    float4 av0, av1, bv0, bv1;
    GEMM_LDG_NN(0)
    GEMM_STS_NN(0)
    __syncthreads();

    int p = 0;
    for (int k0 = 0; k0 < kLen; k0 += 16) {
        bool hasNext = (k0 + 16 < kLen);
        if (hasNext) GEMM_LDG_NN(k0 + 16)
        #pragma unroll
        for (int kk = 0; kk < 16; kk++) GEMM_FRAG_STEP(As[p], Bs[p])
        if (hasNext) {
            GEMM_STS_NN(p ^ 1)
            __syncthreads();
            p ^= 1;
        }
    }

    #pragma unroll
    for (int i = 0; i < 8; i++) {
        int gr = cRow * 128 + tRow * 8 + i;
        #pragma unroll
        for (int j = 0; j < 8; j++) {
            int gc = cCol * 128 + tCol * 8 + j;
            Cp[(size_t)gr * N + gc] = acc[i][j];
        }
    }
}

// ---------------------------------------------------------------------------
// Reduce split-K partials: h[i] += p0+p1+p2 + bias[col]  (N = D_).
// ---------------------------------------------------------------------------
__global__ void reduce3_kernel(const float* __restrict__ P,
                               const float* __restrict__ bias,
                               float* __restrict__ h) {
    int i4 = blockIdx.x * blockDim.x + threadIdx.x;
    size_t base = (size_t)i4 * 4;
    int col = (int)(base % D_);
    const size_t stride = (size_t)T_ * D_;

    float4 p0 = *(const float4*)(P + base);
    float4 p1 = *(const float4*)(P + stride + base);
    float4 p2 = *(const float4*)(P + 2 * stride + base);
    float4 hv = *(const float4*)(h + base);
    float4 bb = *(const float4*)(bias + col);

    float4 r;
    r.x = p0.x + p1.x + p2.x + bb.x + hv.x;
    r.y = p0.y + p1.y + p2.y + bb.y + hv.y;
    r.z = p0.z + p1.z + p2.z + bb.z + hv.z;
    r.w = p0.w + p1.w + p2.w + bb.w + hv.w;
    *(float4*)(h + base) = r;
}

// ---------------------------------------------------------------------------
// SGEMM NT: C[M,N] = A[M,K] @ Bt[N,K]^T  (LM head; N=50257).
// BK=16; B thread loads 8 k-values of one n-column, stored transposed.
// ---------------------------------------------------------------------------
__global__ __launch_bounds__(256) void sgemm_nt(
    int M, int N, int K,
    const float* __restrict__ A, const float* __restrict__ Bt,
    float* __restrict__ C) {
    __shared__ __align__(16) float As[2][16][128];
    __shared__ __align__(16) float Bs[2][16][132];

    int tid  = threadIdx.x;
    int cRow = blockIdx.y, cCol = blockIdx.x;
    int tCol = tid & 15;
    int tRow = tid >> 4;

    int aRow = tid >> 1;
    int aCol = (tid & 1) * 8;
    int bRowT = tid >> 1;         // n within tile, 0..127
    int bColT = (tid & 1) * 8;    // k offset, 0 or 8

    const float* Ap = A + (size_t)cRow * 128 * K + (size_t)aRow * K + aCol;
    int gn = cCol * 128 + bRowT;
    bool nOk = gn < N;
    const float* Bp = Bt + (size_t)(nOk ? gn : 0) * K + bColT;

    float acc[8][8];
    #pragma unroll
    for (int i = 0; i < 8; i++)
        #pragma unroll
        for (int j = 0; j < 8; j++) acc[i][j] = 0.f;

    float4 av0, av1, bv0, bv1;

    #define GEMM_LDG_NT(koff)                                               \
        {                                                                   \
            av0 = *(const float4*)(Ap + (koff));                            \
            av1 = *(const float4*)(Ap + (koff) + 4);                        \
            if (nOk) {                                                      \
                bv0 = *(const float4*)(Bp + (koff));                        \
                bv1 = *(const float4*)(Bp + (koff) + 4);                    \
            } else {                                                        \
                bv0 = make_float4(0.f, 0.f, 0.f, 0.f);                      \
                bv1 = bv0;                                                  \
            }                                                               \
        }

    #define GEMM_STS_NT(q)                                                  \
        {                                                                   \
            As[q][aCol + 0][aRow] = av0.x;                                  \
            As[q][aCol + 1][aRow] = av0.y;                                  \
            As[q][aCol + 2][aRow] = av0.z;                                  \
            As[q][aCol + 3][aRow] = av0.w;                                  \
            As[q][aCol + 4][aRow] = av1.x;                                  \
            As[q][aCol + 5][aRow] = av1.y;                                  \
            As[q][aCol + 6][aRow] = av1.z;                                  \
            As[q][aCol + 7][aRow] = av1.w;                                  \
            Bs[q][bColT + 0][bRowT] = bv0.x;                                \
            Bs[q][bColT + 1][bRowT] = bv0.y;                                \
            Bs[q][bColT + 2][bRowT] = bv0.z;                                \
            Bs[q][bColT + 3][bRowT] = bv0.w;                                \
            Bs[q][bColT + 4][bRowT] = bv1.x;                                \
            Bs[q][bColT + 5][bRowT] = bv1.y;                                \
            Bs[q][bColT + 6][bRowT] = bv1.z;                                \
            Bs[q][bColT + 7][bRowT] = bv1.w;                                \
        }

    GEMM_LDG_NT(0)
    GEMM_STS_NT(0)
    __syncthreads();

    int p = 0;
    for (int k0 = 0; k0 < K; k0 += 16) {
        bool hasNext = (k0 + 16 < K);
        if (hasNext) GEMM_LDG_NT(k0 + 16)
        #pragma unroll
        for (int kk = 0; kk < 16; kk++) GEMM_FRAG_STEP(As[p], Bs[p])
        if (hasNext) {
            GEMM_STS_NT(p ^ 1)
            __syncthreads();
            p ^= 1;
        }
    }

    #pragma unroll
    for (int i = 0; i < 8; i++) {
        int gr = cRow * 128 + tRow * 8 + i;
        #pragma unroll
        for (int j = 0; j < 8; j++) {
            int gc = cCol * 128 + tCol * 8 + j;
            if (gc < N) C[(size_t)gr * N + gc] = acc[i][j];
        }
    }
}

// ---------------------------------------------------------------------------
// Launch sequence
// ---------------------------------------------------------------------------
extern "C" void kernel_launch(void* const* d_in, const int* in_sizes, int n_in,
                              void* d_out, int out_size) {
    const float* x     = (const float*)d_in[0];
    const float* Wqkv  = (const float*)d_in[1];
    const float* bqkv  = (const float*)d_in[2];
    const float* Wo    = (const float*)d_in[3];
    const float* bo    = (const float*)d_in[4];
    const float* W1    = (const float*)d_in[5];
    const float* b1    = (const float*)d_in[6];
    const float* W2    = (const float*)d_in[7];
    const float* b2    = (const float*)d_in[8];
    const float* ln1g  = (const float*)d_in[9];
    const float* ln1b  = (const float*)d_in[10];
    const float* ln2g  = (const float*)d_in[11];
    const float* ln2b  = (const float*)d_in[12];
    const float* lnfg  = (const float*)d_in[13];
    const float* lnfb  = (const float*)d_in[14];
    const float* Wlm   = (const float*)d_in[15];
    float* out = (float*)d_out;

    float *h, *a, *qkv, *att, *ff, *part;
    cudaGetSymbolAddress((void**)&h,    g_h);
    cudaGetSymbolAddress((void**)&a,    g_a);
    cudaGetSymbolAddress((void**)&qkv,  g_qkv);
    cudaGetSymbolAddress((void**)&att,  g_att);
    cudaGetSymbolAddress((void**)&ff,   g_ff);
    cudaGetSymbolAddress((void**)&part, g_part);

    cudaMemcpyAsync(h, x, (size_t)T_ * D_ * sizeof(float),
                    cudaMemcpyDeviceToDevice);

    const int redBlocks = (T_ * D_ / 4) / 256;   // 1536

    for (int l = 0; l < L_; l++) {
        const float* wqkv = Wqkv + (size_t)l * D_ * 3 * D_;
        const float* bq   = bqkv + (size_t)l * 3 * D_;
        const float* wo   = Wo   + (size_t)l * D_ * D_;
        const float* bol  = bo   + (size_t)l * D_;
        const float* w1   = W1   + (size_t)l * D_ * DFF_;
        const float* b1l  = b1   + (size_t)l * DFF_;
        const float* w2   = W2   + (size_t)l * DFF_ * D_;
        const float* b2l  = b2   + (size_t)l * D_;

        // LN1
        ln_kernel<<<T_, 256>>>(h, ln1g + l * D_, ln1b + l * D_, a);
        // QKV (288 CTAs)
        sgemm_nn<<<dim3(3 * D_ / 128, T_ / 128), 256>>>(
            T_, 3 * D_, D_, a, wqkv, bq, nullptr, qkv, 0);
        // tiled attention (192 blocks, 128 thr)
        attn_kernel<<<B_ * H_ * NQB, 128>>>(qkv, att);
        // O proj: split-K x3 + reduce(bias+residual)
        sgemm_nn_splitk<<<dim3(D_ / 128, T_ / 128, NSPLIT), 256>>>(
            T_, D_, D_, D_ / NSPLIT, att, wo, part);
        reduce3_kernel<<<redBlocks, 256>>>(part, bol, h);
        // LN2
        ln_kernel<<<T_, 256>>>(h, ln2g + l * D_, ln2b + l * D_, a);
        // FFN1 + gelu (384 CTAs)
        sgemm_nn<<<dim3(DFF_ / 128, T_ / 128), 256>>>(
            T_, DFF_, D_, a, w1, b1l, nullptr, ff, 1);
        // FFN2: split-K x3 + reduce(bias+residual)
        sgemm_nn_splitk<<<dim3(D_ / 128, T_ / 128, NSPLIT), 256>>>(
            T_, D_, DFF_, DFF_ / NSPLIT, ff, w2, part);
        reduce3_kernel<<<redBlocks, 256>>>(part, b2l, h);
    }

    // final LN + LM head
    ln_kernel<<<T_, 256>>>(h, lnfg, lnfb, a);
    sgemm_nt<<<dim3((V_ + 127) / 128, T_ / 128), 256>>>(
        T_, V_, D_, a, Wlm, out);
}

// round 10
// speedup vs baseline: 1.1558x; 1.1558x over previous
#include <cuda_runtime.h>
#include <cuda_bf16.h>
#include <math.h>

// ---------------------------------------------------------------------------
// GPT-2 forward (B=2, S=1024, D=768, H=12, L=12, vocab=50257).
// Round 9: round-8 tf32 tensor-core GEMM (mma.sync.m16n8k8, 3-term split),
// re-audited; As padded 128->132 to kill 4-way bank conflicts on A-fragment
// scalar LDS (Bs was already padded). Baseline to beat: 16008us (FFMA).
// ---------------------------------------------------------------------------

#define B_   2
#define S_   1024
#define T_   (B_ * S_)        // 2048 tokens
#define D_   768
#define H_   12
#define HD_  64
#define DFF_ 3072
#define L_   12
#define V_   50257
#define ATT_SCALE 0.125f      // 1/sqrt(64)
#define NSPLIT 3
#define NQB  (S_ / 128)       // q-blocks per (b,h) = 8

// Scratch (device globals — no allocation allowed)
__device__ float g_h[T_ * D_];            // residual stream
__device__ float g_a[T_ * D_];            // LN output
__device__ float g_qkv[T_ * 3 * D_];      // qkv
__device__ float g_att[T_ * D_];          // attention output
__device__ float g_ff[T_ * DFF_];         // FFN hidden
__device__ float g_part[NSPLIT * T_ * D_];// split-K partials (narrow GEMMs)

// ---------------------------------------------------------------------------
// LayerNorm: one block (256 threads) per token row of 768.
// ---------------------------------------------------------------------------
__global__ void ln_kernel(const float* __restrict__ x,
                          const float* __restrict__ g,
                          const float* __restrict__ b,
                          float* __restrict__ y) {
    int row = blockIdx.x;
    const float* xr = x + (size_t)row * D_;
    int t = threadIdx.x;

    float a0 = xr[t], a1 = xr[t + 256], a2 = xr[t + 512];
    float s = a0 + a1 + a2;

    __shared__ float sh[8];
    #pragma unroll
    for (int o = 16; o; o >>= 1) s += __shfl_xor_sync(0xffffffffu, s, o);
    if ((t & 31) == 0) sh[t >> 5] = s;
    __syncthreads();
    float tot = 0.f;
    #pragma unroll
    for (int i = 0; i < 8; i++) tot += sh[i];
    float mean = tot * (1.0f / 768.0f);

    float d0 = a0 - mean, d1 = a1 - mean, d2 = a2 - mean;
    float vs = d0 * d0 + d1 * d1 + d2 * d2;
    __syncthreads();
    #pragma unroll
    for (int o = 16; o; o >>= 1) vs += __shfl_xor_sync(0xffffffffu, vs, o);
    if ((t & 31) == 0) sh[t >> 5] = vs;
    __syncthreads();
    float vtot = 0.f;
    #pragma unroll
    for (int i = 0; i < 8; i++) vtot += sh[i];
    float inv = rsqrtf(vtot * (1.0f / 768.0f) + 1e-5f);

    float* yr = y + (size_t)row * D_;
    yr[t]       = d0 * inv * g[t]       + b[t];
    yr[t + 256] = d1 * inv * g[t + 256] + b[t + 256];
    yr[t + 512] = d2 * inv * g[t + 512] + b[t + 512];
}

// ---------------------------------------------------------------------------
// Tiled causal attention (unchanged; verified in the 16008us pass).
// ---------------------------------------------------------------------------
__global__ __launch_bounds__(128) void attn_kernel(
    const float* __restrict__ qkv, float* __restrict__ out) {
    __shared__ __align__(16) float Ks[32][64];
    __shared__ __align__(16) float Vs[32][64];

    int bh   = blockIdx.x / NQB;
    int qblk = (NQB - 1) - (blockIdx.x % NQB);   // long blocks first
    int h = bh % H_;
    int b = bh / H_;
    int wid  = threadIdx.x >> 5;
    int lane = threadIdx.x & 31;

    int qg = qblk * 128 + wid * 32 + lane;       // this lane's query
    const float* base = qkv + (size_t)b * S_ * (3 * D_);

    float qr[64];
    const float4* qp = (const float4*)(base + (size_t)qg * (3 * D_) + h * HD_);
    #pragma unroll
    for (int d4 = 0; d4 < 16; d4++) {
        float4 v = qp[d4];
        qr[4 * d4 + 0] = v.x * ATT_SCALE;
        qr[4 * d4 + 1] = v.y * ATT_SCALE;
        qr[4 * d4 + 2] = v.z * ATT_SCALE;
        qr[4 * d4 + 3] = v.w * ATT_SCALE;
    }

    float m = -1e30f, l = 0.f;
    float acc[64];
    #pragma unroll
    for (int d = 0; d < 64; d++) acc[d] = 0.f;

    int my_tiles    = qblk * 4 + wid + 1;
    int block_tiles = qblk * 4 + 4;

    for (int t = 0; t < block_tiles; t++) {
        int jbase = t * 32;
        #pragma unroll
        for (int u = 0; u < 4; u++) {
            int slot = threadIdx.x + u * 128;
            int jr = slot >> 4;
            int c4 = slot & 15;
            const float* rowp = base + (size_t)(jbase + jr) * (3 * D_) + h * HD_ + c4 * 4;
            *(float4*)(&Ks[jr][c4 * 4]) = *(const float4*)(rowp + D_);
            *(float4*)(&Vs[jr][c4 * 4]) = *(const float4*)(rowp + 2 * D_);
        }
        __syncthreads();

        if (t < my_tiles) {
            float s[32];
            float tmax = -1e30f;
            #pragma unroll
            for (int j = 0; j < 32; j++) {
                float s0 = 0.f, s1 = 0.f, s2 = 0.f, s3 = 0.f;
                #pragma unroll
                for (int d4 = 0; d4 < 16; d4++) {
                    float4 kv = *(const float4*)(&Ks[j][d4 * 4]);
                    s0 += qr[4 * d4 + 0] * kv.x;
                    s1 += qr[4 * d4 + 1] * kv.y;
                    s2 += qr[4 * d4 + 2] * kv.z;
                    s3 += qr[4 * d4 + 3] * kv.w;
                }
                float sv = (s0 + s1) + (s2 + s3);
                if (jbase + j > qg) sv = -1e30f;
                s[j] = sv;
                tmax = fmaxf(tmax, sv);
            }
            float mn = fmaxf(m, tmax);
            float c  = __expf(m - mn);
            l *= c;
            #pragma unroll
            for (int d = 0; d < 64; d++) acc[d] *= c;
            #pragma unroll
            for (int j = 0; j < 32; j++) {
                float p = __expf(s[j] - mn);
                l += p;
                #pragma unroll
                for (int d4 = 0; d4 < 16; d4++) {
                    float4 vv = *(const float4*)(&Vs[j][d4 * 4]);
                    acc[4 * d4 + 0] += p * vv.x;
                    acc[4 * d4 + 1] += p * vv.y;
                    acc[4 * d4 + 2] += p * vv.z;
                    acc[4 * d4 + 3] += p * vv.w;
                }
            }
            m = mn;
        }
        __syncthreads();
    }

    float invl = 1.0f / l;
    float4* op = (float4*)(out + (size_t)(b * S_ + qg) * D_ + h * HD_);
    #pragma unroll
    for (int d4 = 0; d4 < 16; d4++) {
        float4 r;
        r.x = acc[4 * d4 + 0] * invl;
        r.y = acc[4 * d4 + 1] * invl;
        r.z = acc[4 * d4 + 2] * invl;
        r.w = acc[4 * d4 + 3] * invl;
        op[d4] = r;
    }
}

// ---------------------------------------------------------------------------
// Tensor-core GEMM engine: mma.sync.m16n8k8 tf32, 3-term split.
// CTA 128x128, 256 thr = 8 warps as 2(M) x 4(N); warp tile 64x32.
// smem: As[buf][k][132] (A transposed, padded), Bs[buf][k][132] (padded).
// Padding 132 = 4 mod 32 -> quad lanes (same grp, tig 0..3) hit banks
// m0 + 4*tig: conflict-free scalar fragment loads for BOTH operands.
// ---------------------------------------------------------------------------
__device__ __forceinline__ void tf32_split(float x, unsigned& hi, unsigned& lo) {
    unsigned h;
    asm("cvt.rna.tf32.f32 %0, %1;" : "=r"(h) : "f"(x));
    float lf = x - __uint_as_float(h);          // exact (Sterbenz)
    unsigned l;
    asm("cvt.rna.tf32.f32 %0, %1;" : "=r"(l) : "f"(lf));
    hi = h; lo = l;
}

__device__ __forceinline__ void mma_tf32(float* d, const unsigned* a,
                                         const unsigned* b) {
    asm("mma.sync.aligned.m16n8k8.row.col.f32.tf32.tf32.f32 "
        "{%0,%1,%2,%3}, {%4,%5,%6,%7}, {%8,%9}, {%0,%1,%2,%3};"
        : "+f"(d[0]), "+f"(d[1]), "+f"(d[2]), "+f"(d[3])
        : "r"(a[0]), "r"(a[1]), "r"(a[2]), "r"(a[3]), "r"(b[0]), "r"(b[1]));
}

// One k8 step: load+split fragments from buffer p at k-offset kk0, 48 mmas.
#define TENSOR_K8(kk0)                                                      \
    {                                                                       \
        unsigned ahi[4][4], alo[4][4], bhi[4][2], blo[4][2];                \
        _Pragma("unroll")                                                   \
        for (int mt = 0; mt < 4; mt++) {                                    \
            int m0 = warpM * 64 + mt * 16 + grp;                            \
            tf32_split(As[p][(kk0) + tig][m0],         ahi[mt][0], alo[mt][0]); \
            tf32_split(As[p][(kk0) + tig][m0 + 8],     ahi[mt][1], alo[mt][1]); \
            tf32_split(As[p][(kk0) + tig + 4][m0],     ahi[mt][2], alo[mt][2]); \
            tf32_split(As[p][(kk0) + tig + 4][m0 + 8], ahi[mt][3], alo[mt][3]); \
        }                                                                   \
        _Pragma("unroll")                                                   \
        for (int nt = 0; nt < 4; nt++) {                                    \
            int n0 = warpN * 32 + nt * 8 + grp;                             \
            tf32_split(Bs[p][(kk0) + tig][n0],     bhi[nt][0], blo[nt][0]); \
            tf32_split(Bs[p][(kk0) + tig + 4][n0], bhi[nt][1], blo[nt][1]); \
        }                                                                   \
        _Pragma("unroll")                                                   \
        for (int mt = 0; mt < 4; mt++)                                      \
            _Pragma("unroll")                                               \
            for (int nt = 0; nt < 4; nt++) {                                \
                mma_tf32(acc[mt][nt], ahi[mt], bhi[nt]);                    \
                mma_tf32(acc[mt][nt], alo[mt], bhi[nt]);                    \
                mma_tf32(acc[mt][nt], ahi[mt], blo[nt]);                    \
            }                                                               \
    }

// Staging macros (round-7 pipeline).
#define GEMM_LDG_NN(koff)                                                   \
    {                                                                       \
        av0 = *(const float4*)(Ap + (koff));                                \
        av1 = *(const float4*)(Ap + (koff) + 4);                            \
        bv0 = *(const float4*)(Bp + (size_t)(koff) * N);                    \
        bv1 = *(const float4*)(Bp + (size_t)((koff) + 8) * N);              \
    }

#define GEMM_STS_NN(q)                                                      \
    {                                                                       \
        As[q][aCol + 0][aRow] = av0.x;                                      \
        As[q][aCol + 1][aRow] = av0.y;                                      \
        As[q][aCol + 2][aRow] = av0.z;                                      \
        As[q][aCol + 3][aRow] = av0.w;                                      \
        As[q][aCol + 4][aRow] = av1.x;                                      \
        As[q][aCol + 5][aRow] = av1.y;                                      \
        As[q][aCol + 6][aRow] = av1.z;                                      \
        As[q][aCol + 7][aRow] = av1.w;                                      \
        *(float4*)(&Bs[q][bRow][bCol])     = bv0;                           \
        *(float4*)(&Bs[q][bRow + 8][bCol]) = bv1;                           \
    }

__device__ __forceinline__ float gelu_erf(float x) {
    return 0.5f * x * (1.0f + erff(x * 0.70710678118654752f));
}

// ---------------------------------------------------------------------------
// SGEMM NN: C[M,N] = A[M,K] @ B[K,N] + bias (+ residual) (+ gelu)
// ---------------------------------------------------------------------------
__global__ __launch_bounds__(256) void sgemm_nn(
    int M, int N, int K,
    const float* __restrict__ A, const float* __restrict__ Bm,
    const float* __restrict__ bias, const float* __restrict__ res,
    float* __restrict__ C, int act) {
    __shared__ __align__(16) float As[2][16][132];
    __shared__ __align__(16) float Bs[2][16][132];

    int tid  = threadIdx.x;
    int cRow = blockIdx.y, cCol = blockIdx.x;
    int lane = tid & 31;
    int warpId = tid >> 5;
    int warpM = warpId & 1;       // 2 warps in M
    int warpN = warpId >> 1;      // 4 warps in N
    int grp = lane >> 2;
    int tig = lane & 3;

    int aRow = tid >> 1;
    int aCol = (tid & 1) * 8;
    int bRow = tid >> 5;
    int bCol = (tid & 31) * 4;

    const float* Ap = A + (size_t)cRow * 128 * K + (size_t)aRow * K + aCol;
    const float* Bp = Bm + cCol * 128 + (size_t)bRow * N + bCol;

    float acc[4][4][4];
    #pragma unroll
    for (int i = 0; i < 4; i++)
        #pragma unroll
        for (int j = 0; j < 4; j++)
            #pragma unroll
            for (int q = 0; q < 4; q++) acc[i][j][q] = 0.f;

    float4 av0, av1, bv0, bv1;
    GEMM_LDG_NN(0)
    GEMM_STS_NN(0)
    __syncthreads();

    int p = 0;
    for (int k0 = 0; k0 < K; k0 += 16) {
        bool hasNext = (k0 + 16 < K);
        if (hasNext) GEMM_LDG_NN(k0 + 16)
        TENSOR_K8(0)
        TENSOR_K8(8)
        if (hasNext) {
            GEMM_STS_NN(p ^ 1)
            __syncthreads();
            p ^= 1;
        }
    }

    #pragma unroll
    for (int mt = 0; mt < 4; mt++) {
        #pragma unroll
        for (int nt = 0; nt < 4; nt++) {
            int r0 = cRow * 128 + warpM * 64 + mt * 16 + grp;
            int c0 = cCol * 128 + warpN * 32 + nt * 8 + 2 * tig;
            #pragma unroll
            for (int half = 0; half < 2; half++) {
                int gr = r0 + half * 8;
                float v0 = acc[mt][nt][2 * half + 0] + bias[c0];
                float v1 = acc[mt][nt][2 * half + 1] + bias[c0 + 1];
                if (act == 1) { v0 = gelu_erf(v0); v1 = gelu_erf(v1); }
                if (res) {
                    v0 += res[(size_t)gr * N + c0];
                    v1 += res[(size_t)gr * N + c0 + 1];
                }
                C[(size_t)gr * N + c0]     = v0;
                C[(size_t)gr * N + c0 + 1] = v1;
            }
        }
    }
}

// ---------------------------------------------------------------------------
// Split-K SGEMM NN: P[z][M,N] = A slab @ B slab. Partials only.
// ---------------------------------------------------------------------------
__global__ __launch_bounds__(256) void sgemm_nn_splitk(
    int M, int N, int K, int kLen,
    const float* __restrict__ A, const float* __restrict__ Bm,
    float* __restrict__ P) {
    __shared__ __align__(16) float As[2][16][132];
    __shared__ __align__(16) float Bs[2][16][132];

    int tid  = threadIdx.x;
    int cRow = blockIdx.y, cCol = blockIdx.x;
    int kOff = blockIdx.z * kLen;
    int lane = tid & 31;
    int warpId = tid >> 5;
    int warpM = warpId & 1;
    int warpN = warpId >> 1;
    int grp = lane >> 2;
    int tig = lane & 3;

    int aRow = tid >> 1;
    int aCol = (tid & 1) * 8;
    int bRow = tid >> 5;
    int bCol = (tid & 31) * 4;

    const float* Ap = A + (size_t)cRow * 128 * K + (size_t)aRow * K + kOff + aCol;
    const float* Bp = Bm + cCol * 128 + (size_t)(kOff + bRow) * N + bCol;
    float* Cp = P + (size_t)blockIdx.z * M * N;

    float acc[4][4][4];
    #pragma unroll
    for (int i = 0; i < 4; i++)
        #pragma unroll
        for (int j = 0; j < 4; j++)
            #pragma unroll
            for (int q = 0; q < 4; q++) acc[i][j][q] = 0.f;

    float4 av0, av1, bv0, bv1;
    GEMM_LDG_NN(0)
    GEMM_STS_NN(0)
    __syncthreads();

    int p = 0;
    for (int k0 = 0; k0 < kLen; k0 += 16) {
        bool hasNext = (k0 + 16 < kLen);
        if (hasNext) GEMM_LDG_NN(k0 + 16)
        TENSOR_K8(0)
        TENSOR_K8(8)
        if (hasNext) {
            GEMM_STS_NN(p ^ 1)
            __syncthreads();
            p ^= 1;
        }
    }

    #pragma unroll
    for (int mt = 0; mt < 4; mt++) {
        #pragma unroll
        for (int nt = 0; nt < 4; nt++) {
            int r0 = cRow * 128 + warpM * 64 + mt * 16 + grp;
            int c0 = cCol * 128 + warpN * 32 + nt * 8 + 2 * tig;
            #pragma unroll
            for (int half = 0; half < 2; half++) {
                int gr = r0 + half * 8;
                Cp[(size_t)gr * N + c0]     = acc[mt][nt][2 * half + 0];
                Cp[(size_t)gr * N + c0 + 1] = acc[mt][nt][2 * half + 1];
            }
        }
    }
}

// ---------------------------------------------------------------------------
// Reduce split-K partials: h[i] += p0+p1+p2 + bias[col]  (N = D_).
// ---------------------------------------------------------------------------
__global__ void reduce3_kernel(const float* __restrict__ P,
                               const float* __restrict__ bias,
                               float* __restrict__ h) {
    int i4 = blockIdx.x * blockDim.x + threadIdx.x;
    size_t base = (size_t)i4 * 4;
    int col = (int)(base % D_);
    const size_t stride = (size_t)T_ * D_;

    float4 p0 = *(const float4*)(P + base);
    float4 p1 = *(const float4*)(P + stride + base);
    float4 p2 = *(const float4*)(P + 2 * stride + base);
    float4 hv = *(const float4*)(h + base);
    float4 bb = *(const float4*)(bias + col);

    float4 r;
    r.x = p0.x + p1.x + p2.x + bb.x + hv.x;
    r.y = p0.y + p1.y + p2.y + bb.y + hv.y;
    r.z = p0.z + p1.z + p2.z + bb.z + hv.z;
    r.w = p0.w + p1.w + p2.w + bb.w + hv.w;
    *(float4*)(h + base) = r;
}

// ---------------------------------------------------------------------------
// SGEMM NT: C[M,N] = A[M,K] @ Bt[N,K]^T  (LM head; N=50257, guarded).
// ---------------------------------------------------------------------------
__global__ __launch_bounds__(256) void sgemm_nt(
    int M, int N, int K,
    const float* __restrict__ A, const float* __restrict__ Bt,
    float* __restrict__ C) {
    __shared__ __align__(16) float As[2][16][132];
    __shared__ __align__(16) float Bs[2][16][132];

    int tid  = threadIdx.x;
    int cRow = blockIdx.y, cCol = blockIdx.x;
    int lane = tid & 31;
    int warpId = tid >> 5;
    int warpM = warpId & 1;
    int warpN = warpId >> 1;
    int grp = lane >> 2;
    int tig = lane & 3;

    int aRow = tid >> 1;
    int aCol = (tid & 1) * 8;
    int bRowT = tid >> 1;         // n within tile, 0..127
    int bColT = (tid & 1) * 8;    // k offset, 0 or 8

    const float* Ap = A + (size_t)cRow * 128 * K + (size_t)aRow * K + aCol;
    int gn = cCol * 128 + bRowT;
    bool nOk = gn < N;
    const float* Bp = Bt + (size_t)(nOk ? gn : 0) * K + bColT;

    float acc[4][4][4];
    #pragma unroll
    for (int i = 0; i < 4; i++)
        #pragma unroll
        for (int j = 0; j < 4; j++)
            #pragma unroll
            for (int q = 0; q < 4; q++) acc[i][j][q] = 0.f;

    float4 av0, av1, bv0, bv1;

    #define GEMM_LDG_NT(koff)                                               \
        {                                                                   \
            av0 = *(const float4*)(Ap + (koff));                            \
            av1 = *(const float4*)(Ap + (koff) + 4);                        \
            if (nOk) {                                                      \
                bv0 = *(const float4*)(Bp + (koff));                        \
                bv1 = *(const float4*)(Bp + (koff) + 4);                    \
            } else {                                                        \
                bv0 = make_float4(0.f, 0.f, 0.f, 0.f);                      \
                bv1 = bv0;                                                  \
            }                                                               \
        }

    #define GEMM_STS_NT(q)                                                  \
        {                                                                   \
            As[q][aCol + 0][aRow] = av0.x;                                  \
            As[q][aCol + 1][aRow] = av0.y;                                  \
            As[q][aCol + 2][aRow] = av0.z;                                  \
            As[q][aCol + 3][aRow] = av0.w;                                  \
            As[q][aCol + 4][aRow] = av1.x;                                  \
            As[q][aCol + 5][aRow] = av1.y;                                  \
            As[q][aCol + 6][aRow] = av1.z;                                  \
            As[q][aCol + 7][aRow] = av1.w;                                  \
            Bs[q][bColT + 0][bRowT] = bv0.x;                                \
            Bs[q][bColT + 1][bRowT] = bv0.y;                                \
            Bs[q][bColT + 2][bRowT] = bv0.z;                                \
            Bs[q][bColT + 3][bRowT] = bv0.w;                                \
            Bs[q][bColT + 4][bRowT] = bv1.x;                                \
            Bs[q][bColT + 5][bRowT] = bv1.y;                                \
            Bs[q][bColT + 6][bRowT] = bv1.z;                                \
            Bs[q][bColT + 7][bRowT] = bv1.w;                                \
        }

    GEMM_LDG_NT(0)
    GEMM_STS_NT(0)
    __syncthreads();

    int p = 0;
    for (int k0 = 0; k0 < K; k0 += 16) {
        bool hasNext = (k0 + 16 < K);
        if (hasNext) GEMM_LDG_NT(k0 + 16)
        TENSOR_K8(0)
        TENSOR_K8(8)
        if (hasNext) {
            GEMM_STS_NT(p ^ 1)
            __syncthreads();
            p ^= 1;
        }
    }

    #pragma unroll
    for (int mt = 0; mt < 4; mt++) {
        #pragma unroll
        for (int nt = 0; nt < 4; nt++) {
            int r0 = cRow * 128 + warpM * 64 + mt * 16 + grp;
            int c0 = cCol * 128 + warpN * 32 + nt * 8 + 2 * tig;
            #pragma unroll
            for (int half = 0; half < 2; half++) {
                int gr = r0 + half * 8;
                if (c0 < N)     C[(size_t)gr * N + c0]     = acc[mt][nt][2 * half + 0];
                if (c0 + 1 < N) C[(size_t)gr * N + c0 + 1] = acc[mt][nt][2 * half + 1];
            }
        }
    }
}

// ---------------------------------------------------------------------------
// Launch sequence (unchanged)
// ---------------------------------------------------------------------------
extern "C" void kernel_launch(void* const* d_in, const int* in_sizes, int n_in,
                              void* d_out, int out_size) {
    const float* x     = (const float*)d_in[0];
    const float* Wqkv  = (const float*)d_in[1];
    const float* bqkv  = (const float*)d_in[2];
    const float* Wo    = (const float*)d_in[3];
    const float* bo    = (const float*)d_in[4];
    const float* W1    = (const float*)d_in[5];
    const float* b1    = (const float*)d_in[6];
    const float* W2    = (const float*)d_in[7];
    const float* b2    = (const float*)d_in[8];
    const float* ln1g  = (const float*)d_in[9];
    const float* ln1b  = (const float*)d_in[10];
    const float* ln2g  = (const float*)d_in[11];
    const float* ln2b  = (const float*)d_in[12];
    const float* lnfg  = (const float*)d_in[13];
    const float* lnfb  = (const float*)d_in[14];
    const float* Wlm   = (const float*)d_in[15];
    float* out = (float*)d_out;

    float *h, *a, *qkv, *att, *ff, *part;
    cudaGetSymbolAddress((void**)&h,    g_h);
    cudaGetSymbolAddress((void**)&a,    g_a);
    cudaGetSymbolAddress((void**)&qkv,  g_qkv);
    cudaGetSymbolAddress((void**)&att,  g_att);
    cudaGetSymbolAddress((void**)&ff,   g_ff);
    cudaGetSymbolAddress((void**)&part, g_part);

    cudaMemcpyAsync(h, x, (size_t)T_ * D_ * sizeof(float),
                    cudaMemcpyDeviceToDevice);

    const int redBlocks = (T_ * D_ / 4) / 256;   // 1536

    for (int l = 0; l < L_; l++) {
        const float* wqkv = Wqkv + (size_t)l * D_ * 3 * D_;
        const float* bq   = bqkv + (size_t)l * 3 * D_;
        const float* wo   = Wo   + (size_t)l * D_ * D_;
        const float* bol  = bo   + (size_t)l * D_;
        const float* w1   = W1   + (size_t)l * D_ * DFF_;
        const float* b1l  = b1   + (size_t)l * DFF_;
        const float* w2   = W2   + (size_t)l * DFF_ * D_;
        const float* b2l  = b2   + (size_t)l * D_;

        ln_kernel<<<T_, 256>>>(h, ln1g + l * D_, ln1b + l * D_, a);
        sgemm_nn<<<dim3(3 * D_ / 128, T_ / 128), 256>>>(
            T_, 3 * D_, D_, a, wqkv, bq, nullptr, qkv, 0);
        attn_kernel<<<B_ * H_ * NQB, 128>>>(qkv, att);
        sgemm_nn_splitk<<<dim3(D_ / 128, T_ / 128, NSPLIT), 256>>>(
            T_, D_, D_, D_ / NSPLIT, att, wo, part);
        reduce3_kernel<<<redBlocks, 256>>>(part, bol, h);
        ln_kernel<<<T_, 256>>>(h, ln2g + l * D_, ln2b + l * D_, a);
        sgemm_nn<<<dim3(DFF_ / 128, T_ / 128), 256>>>(
            T_, DFF_, D_, a, w1, b1l, nullptr, ff, 1);
        sgemm_nn_splitk<<<dim3(D_ / 128, T_ / 128, NSPLIT), 256>>>(
            T_, D_, DFF_, DFF_ / NSPLIT, ff, w2, part);
        reduce3_kernel<<<redBlocks, 256>>>(part, b2l, h);
    }

    ln_kernel<<<T_, 256>>>(h, lnfg, lnfb, a);
    sgemm_nt<<<dim3((V_ + 127) / 128, T_ / 128), 256>>>(
        T_, V_, D_, a, Wlm, out);
}

// round 17
// speedup vs baseline: 1.5104x; 1.3069x over previous
#include <cuda_runtime.h>
#include <cuda_bf16.h>
#include <cuda_fp16.h>
#include <math.h>

// ---------------------------------------------------------------------------
// GPT-2 forward (B=2, S=1024, D=768, H=12, L=12, vocab=50257).
// Round 16: fp16x2-split GEMM engine (mma.m16n8k16.f16, Markidis 2-term
// split, 3 mmas per K16 tile; split ONCE at smem-store time). Triple-
// audited; held stable through broker starvation.
// Baseline to beat: 13850.7us (tf32x3).
// ---------------------------------------------------------------------------

#define B_   2
#define S_   1024
#define T_   (B_ * S_)        // 2048 tokens
#define D_   768
#define H_   12
#define HD_  64
#define DFF_ 3072
#define L_   12
#define V_   50257
#define ATT_SCALE 0.125f      // 1/sqrt(64)
#define NSPLIT 3
#define NQB  (S_ / 128)       // q-blocks per (b,h) = 8

// Scratch (device globals — no allocation allowed)
__device__ float g_h[T_ * D_];
__device__ float g_a[T_ * D_];
__device__ float g_qkv[T_ * 3 * D_];
__device__ float g_att[T_ * D_];
__device__ float g_ff[T_ * DFF_];
__device__ float g_part[NSPLIT * T_ * D_];

// ---------------------------------------------------------------------------
// LayerNorm (unchanged, verified).
// ---------------------------------------------------------------------------
__global__ void ln_kernel(const float* __restrict__ x,
                          const float* __restrict__ g,
                          const float* __restrict__ b,
                          float* __restrict__ y) {
    int row = blockIdx.x;
    const float* xr = x + (size_t)row * D_;
    int t = threadIdx.x;

    float a0 = xr[t], a1 = xr[t + 256], a2 = xr[t + 512];
    float s = a0 + a1 + a2;

    __shared__ float sh[8];
    #pragma unroll
    for (int o = 16; o; o >>= 1) s += __shfl_xor_sync(0xffffffffu, s, o);
    if ((t & 31) == 0) sh[t >> 5] = s;
    __syncthreads();
    float tot = 0.f;
    #pragma unroll
    for (int i = 0; i < 8; i++) tot += sh[i];
    float mean = tot * (1.0f / 768.0f);

    float d0 = a0 - mean, d1 = a1 - mean, d2 = a2 - mean;
    float vs = d0 * d0 + d1 * d1 + d2 * d2;
    __syncthreads();
    #pragma unroll
    for (int o = 16; o; o >>= 1) vs += __shfl_xor_sync(0xffffffffu, vs, o);
    if ((t & 31) == 0) sh[t >> 5] = vs;
    __syncthreads();
    float vtot = 0.f;
    #pragma unroll
    for (int i = 0; i < 8; i++) vtot += sh[i];
    float inv = rsqrtf(vtot * (1.0f / 768.0f) + 1e-5f);

    float* yr = y + (size_t)row * D_;
    yr[t]       = d0 * inv * g[t]       + b[t];
    yr[t + 256] = d1 * inv * g[t + 256] + b[t + 256];
    yr[t + 512] = d2 * inv * g[t + 512] + b[t + 512];
}

// ---------------------------------------------------------------------------
// Tiled causal attention (unchanged, verified in both passes).
// ---------------------------------------------------------------------------
__global__ __launch_bounds__(128) void attn_kernel(
    const float* __restrict__ qkv, float* __restrict__ out) {
    __shared__ __align__(16) float Ks[32][64];
    __shared__ __align__(16) float Vs[32][64];

    int bh   = blockIdx.x / NQB;
    int qblk = (NQB - 1) - (blockIdx.x % NQB);
    int h = bh % H_;
    int b = bh / H_;
    int wid  = threadIdx.x >> 5;
    int lane = threadIdx.x & 31;

    int qg = qblk * 128 + wid * 32 + lane;
    const float* base = qkv + (size_t)b * S_ * (3 * D_);

    float qr[64];
    const float4* qp = (const float4*)(base + (size_t)qg * (3 * D_) + h * HD_);
    #pragma unroll
    for (int d4 = 0; d4 < 16; d4++) {
        float4 v = qp[d4];
        qr[4 * d4 + 0] = v.x * ATT_SCALE;
        qr[4 * d4 + 1] = v.y * ATT_SCALE;
        qr[4 * d4 + 2] = v.z * ATT_SCALE;
        qr[4 * d4 + 3] = v.w * ATT_SCALE;
    }

    float m = -1e30f, l = 0.f;
    float acc[64];
    #pragma unroll
    for (int d = 0; d < 64; d++) acc[d] = 0.f;

    int my_tiles    = qblk * 4 + wid + 1;
    int block_tiles = qblk * 4 + 4;

    for (int t = 0; t < block_tiles; t++) {
        int jbase = t * 32;
        #pragma unroll
        for (int u = 0; u < 4; u++) {
            int slot = threadIdx.x + u * 128;
            int jr = slot >> 4;
            int c4 = slot & 15;
            const float* rowp = base + (size_t)(jbase + jr) * (3 * D_) + h * HD_ + c4 * 4;
            *(float4*)(&Ks[jr][c4 * 4]) = *(const float4*)(rowp + D_);
            *(float4*)(&Vs[jr][c4 * 4]) = *(const float4*)(rowp + 2 * D_);
        }
        __syncthreads();

        if (t < my_tiles) {
            float s[32];
            float tmax = -1e30f;
            #pragma unroll
            for (int j = 0; j < 32; j++) {
                float s0 = 0.f, s1 = 0.f, s2 = 0.f, s3 = 0.f;
                #pragma unroll
                for (int d4 = 0; d4 < 16; d4++) {
                    float4 kv = *(const float4*)(&Ks[j][d4 * 4]);
                    s0 += qr[4 * d4 + 0] * kv.x;
                    s1 += qr[4 * d4 + 1] * kv.y;
                    s2 += qr[4 * d4 + 2] * kv.z;
                    s3 += qr[4 * d4 + 3] * kv.w;
                }
                float sv = (s0 + s1) + (s2 + s3);
                if (jbase + j > qg) sv = -1e30f;
                s[j] = sv;
                tmax = fmaxf(tmax, sv);
            }
            float mn = fmaxf(m, tmax);
            float c  = __expf(m - mn);
            l *= c;
            #pragma unroll
            for (int d = 0; d < 64; d++) acc[d] *= c;
            #pragma unroll
            for (int j = 0; j < 32; j++) {
                float p = __expf(s[j] - mn);
                l += p;
                #pragma unroll
                for (int d4 = 0; d4 < 16; d4++) {
                    float4 vv = *(const float4*)(&Vs[j][d4 * 4]);
                    acc[4 * d4 + 0] += p * vv.x;
                    acc[4 * d4 + 1] += p * vv.y;
                    acc[4 * d4 + 2] += p * vv.z;
                    acc[4 * d4 + 3] += p * vv.w;
                }
            }
            m = mn;
        }
        __syncthreads();
    }

    float invl = 1.0f / l;
    float4* op = (float4*)(out + (size_t)(b * S_ + qg) * D_ + h * HD_);
    #pragma unroll
    for (int d4 = 0; d4 < 16; d4++) {
        float4 r;
        r.x = acc[4 * d4 + 0] * invl;
        r.y = acc[4 * d4 + 1] * invl;
        r.z = acc[4 * d4 + 2] * invl;
        r.w = acc[4 * d4 + 3] * invl;
        op[d4] = r;
    }
}

// ---------------------------------------------------------------------------
// fp16x2-split GEMM engine. mma.m16n8k16.f16, CTA 128x128, 8 warps
// 2(M)x4(N), warp tile 64x32. smem: pre-split packed k-pair planes
//   Ahi/Alo[buf][k2][132] : (h16(A[2k2+1,m])<<16)|h16(A[2k2,m])  (m index)
//   Bhi/Blo[buf][k2][132] : (h16(B[2k2+1,n])<<16)|h16(B[2k2,n])  (n index)
// m16n8k16 fragments (row.col): a0=(row grp, k 2tig..)->Ahi[tig][m0],
// a1=[tig][m0+8], a2=[tig+4][m0], a3=[tig+4][m0+8]; b0=Bhi[tig][n0],
// b1=Bhi[tig+4][n0]. 132 pad (=4 mod 32) -> conflict-free quad access.
// ---------------------------------------------------------------------------
__device__ __forceinline__ void f16x2_split(float x0, float x1,
                                            unsigned& hi, unsigned& lo) {
    __half h0 = __float2half_rn(x0);
    __half h1 = __float2half_rn(x1);
    __half l0 = __float2half_rn(x0 - __half2float(h0));
    __half l1 = __float2half_rn(x1 - __half2float(h1));
    hi = ((unsigned)__half_as_ushort(h1) << 16) | __half_as_ushort(h0);
    lo = ((unsigned)__half_as_ushort(l1) << 16) | __half_as_ushort(l0);
}

__device__ __forceinline__ void mma_f16(float* d, const unsigned* a,
                                        const unsigned* b) {
    asm("mma.sync.aligned.m16n8k16.row.col.f32.f16.f16.f32 "
        "{%0,%1,%2,%3}, {%4,%5,%6,%7}, {%8,%9}, {%0,%1,%2,%3};"
        : "+f"(d[0]), "+f"(d[1]), "+f"(d[2]), "+f"(d[3])
        : "r"(a[0]), "r"(a[1]), "r"(a[2]), "r"(a[3]), "r"(b[0]), "r"(b[1]));
}

// One BK=16 slab of tensor work from buffer p: 16 tiles x 3 mmas.
#define TENSOR_K16()                                                        \
    {                                                                       \
        unsigned bhi[4][2], blo[4][2];                                      \
        _Pragma("unroll")                                                   \
        for (int nt = 0; nt < 4; nt++) {                                    \
            int n0 = warpN * 32 + nt * 8 + grp;                             \
            bhi[nt][0] = Bhi[p][tig][n0];                                   \
            bhi[nt][1] = Bhi[p][tig + 4][n0];                               \
            blo[nt][0] = Blo[p][tig][n0];                                   \
            blo[nt][1] = Blo[p][tig + 4][n0];                               \
        }                                                                   \
        _Pragma("unroll")                                                   \
        for (int mt = 0; mt < 4; mt++) {                                    \
            int m0 = warpM * 64 + mt * 16 + grp;                            \
            unsigned ahi[4], alo[4];                                        \
            ahi[0] = Ahi[p][tig][m0];     alo[0] = Alo[p][tig][m0];         \
            ahi[1] = Ahi[p][tig][m0 + 8]; alo[1] = Alo[p][tig][m0 + 8];     \
            ahi[2] = Ahi[p][tig + 4][m0];     alo[2] = Alo[p][tig + 4][m0]; \
            ahi[3] = Ahi[p][tig + 4][m0 + 8]; alo[3] = Alo[p][tig + 4][m0 + 8]; \
            _Pragma("unroll")                                               \
            for (int nt = 0; nt < 4; nt++) {                                \
                mma_f16(acc[mt][nt], ahi, bhi[nt]);                         \
                mma_f16(acc[mt][nt], ahi, blo[nt]);                         \
                mma_f16(acc[mt][nt], alo, bhi[nt]);                         \
            }                                                               \
        }                                                                   \
    }

// NN staging. A: thread owns row aRow, k-cols aCol..aCol+7 (aCol=(tid&1)*8).
// B: thread owns k-row pair (2*bK2, 2*bK2+1), n-cols bN..bN+3 (bK2=tid>>5).
#define GEMM_LDG_NN(koff)                                                   \
    {                                                                       \
        av0 = *(const float4*)(Ap + (koff));                                \
        av1 = *(const float4*)(Ap + (koff) + 4);                            \
        bv0 = *(const float4*)(Bp + (size_t)(koff) * N);                    \
        bv1 = *(const float4*)(Bp + (size_t)((koff) + 1) * N);              \
    }

#define GEMM_STS_NN(q)                                                     \
    {                                                                      \
        unsigned h_, l_;                                                   \
        f16x2_split(av0.x, av0.y, h_, l_);                                 \
        Ahi[q][aK2 + 0][aRow] = h_; Alo[q][aK2 + 0][aRow] = l_;            \
        f16x2_split(av0.z, av0.w, h_, l_);                                 \
        Ahi[q][aK2 + 1][aRow] = h_; Alo[q][aK2 + 1][aRow] = l_;            \
        f16x2_split(av1.x, av1.y, h_, l_);                                 \
        Ahi[q][aK2 + 2][aRow] = h_; Alo[q][aK2 + 2][aRow] = l_;            \
        f16x2_split(av1.z, av1.w, h_, l_);                                 \
        Ahi[q][aK2 + 3][aRow] = h_; Alo[q][aK2 + 3][aRow] = l_;            \
        unsigned bh_[4], bl_[4];                                           \
        f16x2_split(bv0.x, bv1.x, bh_[0], bl_[0]);                         \
        f16x2_split(bv0.y, bv1.y, bh_[1], bl_[1]);                         \
        f16x2_split(bv0.z, bv1.z, bh_[2], bl_[2]);                         \
        f16x2_split(bv0.w, bv1.w, bh_[3], bl_[3]);                         \
        *(uint4*)(&Bhi[q][bK2][bN]) = make_uint4(bh_[0], bh_[1], bh_[2], bh_[3]); \
        *(uint4*)(&Blo[q][bK2][bN]) = make_uint4(bl_[0], bl_[1], bl_[2], bl_[3]); \
    }

__device__ __forceinline__ float gelu_erf(float x) {
    return 0.5f * x * (1.0f + erff(x * 0.70710678118654752f));
}

// ---------------------------------------------------------------------------
// SGEMM NN: C = A@B + bias (+res)(+gelu)
// ---------------------------------------------------------------------------
__global__ __launch_bounds__(256) void sgemm_nn(
    int M, int N, int K,
    const float* __restrict__ A, const float* __restrict__ Bm,
    const float* __restrict__ bias, const float* __restrict__ res,
    float* __restrict__ C, int act) {
    __shared__ __align__(16) unsigned Ahi[2][8][132], Alo[2][8][132];
    __shared__ __align__(16) unsigned Bhi[2][8][132], Blo[2][8][132];

    int tid  = threadIdx.x;
    int cRow = blockIdx.y, cCol = blockIdx.x;
    int lane = tid & 31;
    int warpId = tid >> 5;
    int warpM = warpId & 1;
    int warpN = warpId >> 1;
    int grp = lane >> 2;
    int tig = lane & 3;

    int aRow = tid >> 1;
    int aCol = (tid & 1) * 8;
    int aK2  = (tid & 1) * 4;
    int bK2  = tid >> 5;          // 0..7
    int bN   = (tid & 31) * 4;

    const float* Ap = A + (size_t)cRow * 128 * K + (size_t)aRow * K + aCol;
    const float* Bp = Bm + cCol * 128 + (size_t)(bK2 * 2) * N + bN;

    float acc[4][4][4];
    #pragma unroll
    for (int i = 0; i < 4; i++)
        #pragma unroll
        for (int j = 0; j < 4; j++)
            #pragma unroll
            for (int q = 0; q < 4; q++) acc[i][j][q] = 0.f;

    float4 av0, av1, bv0, bv1;
    GEMM_LDG_NN(0)
    GEMM_STS_NN(0)
    __syncthreads();

    int p = 0;
    for (int k0 = 0; k0 < K; k0 += 16) {
        bool hasNext = (k0 + 16 < K);
        if (hasNext) GEMM_LDG_NN(k0 + 16)
        TENSOR_K16()
        if (hasNext) {
            GEMM_STS_NN(p ^ 1)
            __syncthreads();
            p ^= 1;
        }
    }

    #pragma unroll
    for (int mt = 0; mt < 4; mt++) {
        #pragma unroll
        for (int nt = 0; nt < 4; nt++) {
            int r0 = cRow * 128 + warpM * 64 + mt * 16 + grp;
            int c0 = cCol * 128 + warpN * 32 + nt * 8 + 2 * tig;
            #pragma unroll
            for (int half = 0; half < 2; half++) {
                int gr = r0 + half * 8;
                float v0 = acc[mt][nt][2 * half + 0] + bias[c0];
                float v1 = acc[mt][nt][2 * half + 1] + bias[c0 + 1];
                if (act == 1) { v0 = gelu_erf(v0); v1 = gelu_erf(v1); }
                if (res) {
                    v0 += res[(size_t)gr * N + c0];
                    v1 += res[(size_t)gr * N + c0 + 1];
                }
                C[(size_t)gr * N + c0]     = v0;
                C[(size_t)gr * N + c0 + 1] = v1;
            }
        }
    }
}

// ---------------------------------------------------------------------------
// Split-K SGEMM NN: partials only.
// ---------------------------------------------------------------------------
__global__ __launch_bounds__(256) void sgemm_nn_splitk(
    int M, int N, int K, int kLen,
    const float* __restrict__ A, const float* __restrict__ Bm,
    float* __restrict__ P) {
    __shared__ __align__(16) unsigned Ahi[2][8][132], Alo[2][8][132];
    __shared__ __align__(16) unsigned Bhi[2][8][132], Blo[2][8][132];

    int tid  = threadIdx.x;
    int cRow = blockIdx.y, cCol = blockIdx.x;
    int kOff = blockIdx.z * kLen;
    int lane = tid & 31;
    int warpId = tid >> 5;
    int warpM = warpId & 1;
    int warpN = warpId >> 1;
    int grp = lane >> 2;
    int tig = lane & 3;

    int aRow = tid >> 1;
    int aCol = (tid & 1) * 8;
    int aK2  = (tid & 1) * 4;
    int bK2  = tid >> 5;
    int bN   = (tid & 31) * 4;

    const float* Ap = A + (size_t)cRow * 128 * K + (size_t)aRow * K + kOff + aCol;
    const float* Bp = Bm + cCol * 128 + (size_t)(kOff + bK2 * 2) * N + bN;
    float* Cp = P + (size_t)blockIdx.z * M * N;

    float acc[4][4][4];
    #pragma unroll
    for (int i = 0; i < 4; i++)
        #pragma unroll
        for (int j = 0; j < 4; j++)
            #pragma unroll
            for (int q = 0; q < 4; q++) acc[i][j][q] = 0.f;

    float4 av0, av1, bv0, bv1;
    GEMM_LDG_NN(0)
    GEMM_STS_NN(0)
    __syncthreads();

    int p = 0;
    for (int k0 = 0; k0 < kLen; k0 += 16) {
        bool hasNext = (k0 + 16 < kLen);
        if (hasNext) GEMM_LDG_NN(k0 + 16)
        TENSOR_K16()
        if (hasNext) {
            GEMM_STS_NN(p ^ 1)
            __syncthreads();
            p ^= 1;
        }
    }

    #pragma unroll
    for (int mt = 0; mt < 4; mt++) {
        #pragma unroll
        for (int nt = 0; nt < 4; nt++) {
            int r0 = cRow * 128 + warpM * 64 + mt * 16 + grp;
            int c0 = cCol * 128 + warpN * 32 + nt * 8 + 2 * tig;
            #pragma unroll
            for (int half = 0; half < 2; half++) {
                int gr = r0 + half * 8;
                Cp[(size_t)gr * N + c0]     = acc[mt][nt][2 * half + 0];
                Cp[(size_t)gr * N + c0 + 1] = acc[mt][nt][2 * half + 1];
            }
        }
    }
}

// ---------------------------------------------------------------------------
// Reduce split-K partials (unchanged).
// ---------------------------------------------------------------------------
__global__ void reduce3_kernel(const float* __restrict__ P,
                               const float* __restrict__ bias,
                               float* __restrict__ h) {
    int i4 = blockIdx.x * blockDim.x + threadIdx.x;
    size_t base = (size_t)i4 * 4;
    int col = (int)(base % D_);
    const size_t stride = (size_t)T_ * D_;

    float4 p0 = *(const float4*)(P + base);
    float4 p1 = *(const float4*)(P + stride + base);
    float4 p2 = *(const float4*)(P + 2 * stride + base);
    float4 hv = *(const float4*)(h + base);
    float4 bb = *(const float4*)(bias + col);

    float4 r;
    r.x = p0.x + p1.x + p2.x + bb.x + hv.x;
    r.y = p0.y + p1.y + p2.y + bb.y + hv.y;
    r.z = p0.z + p1.z + p2.z + bb.z + hv.z;
    r.w = p0.w + p1.w + p2.w + bb.w + hv.w;
    *(float4*)(h + base) = r;
}

// ---------------------------------------------------------------------------
// SGEMM NT: C = A @ Bt^T (LM head; N=50257 guarded).
// ---------------------------------------------------------------------------
__global__ __launch_bounds__(256) void sgemm_nt(
    int M, int N, int K,
    const float* __restrict__ A, const float* __restrict__ Bt,
    float* __restrict__ C) {
    __shared__ __align__(16) unsigned Ahi[2][8][132], Alo[2][8][132];
    __shared__ __align__(16) unsigned Bhi[2][8][132], Blo[2][8][132];

    int tid  = threadIdx.x;
    int cRow = blockIdx.y, cCol = blockIdx.x;
    int lane = tid & 31;
    int warpId = tid >> 5;
    int warpM = warpId & 1;
    int warpN = warpId >> 1;
    int grp = lane >> 2;
    int tig = lane & 3;

    int aRow = tid >> 1;
    int aCol = (tid & 1) * 8;
    int aK2  = (tid & 1) * 4;
    int bRowT = tid >> 1;         // n within tile
    int bColT = (tid & 1) * 8;    // k offset 0/8
    int bK2T  = (tid & 1) * 4;    // k2 offset 0/4

    const float* Ap = A + (size_t)cRow * 128 * K + (size_t)aRow * K + aCol;
    int gn = cCol * 128 + bRowT;
    bool nOk = gn < N;
    const float* Bp = Bt + (size_t)(nOk ? gn : 0) * K + bColT;

    float acc[4][4][4];
    #pragma unroll
    for (int i = 0; i < 4; i++)
        #pragma unroll
        for (int j = 0; j < 4; j++)
            #pragma unroll
            for (int q = 0; q < 4; q++) acc[i][j][q] = 0.f;

    float4 av0, av1, bv0, bv1;

    #define GEMM_LDG_NT(koff)                                               \
        {                                                                   \
            av0 = *(const float4*)(Ap + (koff));                            \
            av1 = *(const float4*)(Ap + (koff) + 4);                        \
            if (nOk) {                                                      \
                bv0 = *(const float4*)(Bp + (koff));                        \
                bv1 = *(const float4*)(Bp + (koff) + 4);                    \
            } else {                                                        \
                bv0 = make_float4(0.f, 0.f, 0.f, 0.f);                      \
                bv1 = bv0;                                                  \
            }                                                               \
        }

    #define GEMM_STS_NT(q)                                                 \
        {                                                                  \
            unsigned h_, l_;                                               \
            f16x2_split(av0.x, av0.y, h_, l_);                             \
            Ahi[q][aK2 + 0][aRow] = h_; Alo[q][aK2 + 0][aRow] = l_;        \
            f16x2_split(av0.z, av0.w, h_, l_);                             \
            Ahi[q][aK2 + 1][aRow] = h_; Alo[q][aK2 + 1][aRow] = l_;        \
            f16x2_split(av1.x, av1.y, h_, l_);                             \
            Ahi[q][aK2 + 2][aRow] = h_; Alo[q][aK2 + 2][aRow] = l_;        \
            f16x2_split(av1.z, av1.w, h_, l_);                             \
            Ahi[q][aK2 + 3][aRow] = h_; Alo[q][aK2 + 3][aRow] = l_;        \
            f16x2_split(bv0.x, bv0.y, h_, l_);                             \
            Bhi[q][bK2T + 0][bRowT] = h_; Blo[q][bK2T + 0][bRowT] = l_;    \
            f16x2_split(bv0.z, bv0.w, h_, l_);                             \
            Bhi[q][bK2T + 1][bRowT] = h_; Blo[q][bK2T + 1][bRowT] = l_;    \
            f16x2_split(bv1.x, bv1.y, h_, l_);                             \
            Bhi[q][bK2T + 2][bRowT] = h_; Blo[q][bK2T + 2][bRowT] = l_;    \
            f16x2_split(bv1.z, bv1.w, h_, l_);                             \
            Bhi[q][bK2T + 3][bRowT] = h_; Blo[q][bK2T + 3][bRowT] = l_;    \
        }

    GEMM_LDG_NT(0)
    GEMM_STS_NT(0)
    __syncthreads();

    int p = 0;
    for (int k0 = 0; k0 < K; k0 += 16) {
        bool hasNext = (k0 + 16 < K);
        if (hasNext) GEMM_LDG_NT(k0 + 16)
        TENSOR_K16()
        if (hasNext) {
            GEMM_STS_NT(p ^ 1)
            __syncthreads();
            p ^= 1;
        }
    }

    #pragma unroll
    for (int mt = 0; mt < 4; mt++) {
        #pragma unroll
        for (int nt = 0; nt < 4; nt++) {
            int r0 = cRow * 128 + warpM * 64 + mt * 16 + grp;
            int c0 = cCol * 128 + warpN * 32 + nt * 8 + 2 * tig;
            #pragma unroll
            for (int half = 0; half < 2; half++) {
                int gr = r0 + half * 8;
                if (c0 < N)     C[(size_t)gr * N + c0]     = acc[mt][nt][2 * half + 0];
                if (c0 + 1 < N) C[(size_t)gr * N + c0 + 1] = acc[mt][nt][2 * half + 1];
            }
        }
    }
}

// ---------------------------------------------------------------------------
// Launch sequence (unchanged)
// ---------------------------------------------------------------------------
extern "C" void kernel_launch(void* const* d_in, const int* in_sizes, int n_in,
                              void* d_out, int out_size) {
    const float* x     = (const float*)d_in[0];
    const float* Wqkv  = (const float*)d_in[1];
    const float* bqkv  = (const float*)d_in[2];
    const float* Wo    = (const float*)d_in[3];
    const float* bo    = (const float*)d_in[4];
    const float* W1    = (const float*)d_in[5];
    const float* b1    = (const float*)d_in[6];
    const float* W2    = (const float*)d_in[7];
    const float* b2    = (const float*)d_in[8];
    const float* ln1g  = (const float*)d_in[9];
    const float* ln1b  = (const float*)d_in[10];
    const float* ln2g  = (const float*)d_in[11];
    const float* ln2b  = (const float*)d_in[12];
    const float* lnfg  = (const float*)d_in[13];
    const float* lnfb  = (const float*)d_in[14];
    const float* Wlm   = (const float*)d_in[15];
    float* out = (float*)d_out;

    float *h, *a, *qkv, *att, *ff, *part;
    cudaGetSymbolAddress((void**)&h,    g_h);
    cudaGetSymbolAddress((void**)&a,    g_a);
    cudaGetSymbolAddress((void**)&qkv,  g_qkv);
    cudaGetSymbolAddress((void**)&att,  g_att);
    cudaGetSymbolAddress((void**)&ff,   g_ff);
    cudaGetSymbolAddress((void**)&part, g_part);

    cudaMemcpyAsync(h, x, (size_t)T_ * D_ * sizeof(float),
                    cudaMemcpyDeviceToDevice);

    const int redBlocks = (T_ * D_ / 4) / 256;   // 1536

    for (int l = 0; l < L_; l++) {
        const float* wqkv = Wqkv + (size_t)l * D_ * 3 * D_;
        const float* bq   = bqkv + (size_t)l * 3 * D_;
        const float* wo   = Wo   + (size_t)l * D_ * D_;
        const float* bol  = bo   + (size_t)l * D_;
        const float* w1   = W1   + (size_t)l * D_ * DFF_;
        const float* b1l  = b1   + (size_t)l * DFF_;
        const float* w2   = W2   + (size_t)l * DFF_ * D_;
        const float* b2l  = b2   + (size_t)l * D_;

        ln_kernel<<<T_, 256>>>(h, ln1g + l * D_, ln1b + l * D_, a);
        sgemm_nn<<<dim3(3 * D_ / 128, T_ / 128), 256>>>(
            T_, 3 * D_, D_, a, wqkv, bq, nullptr, qkv, 0);
        attn_kernel<<<B_ * H_ * NQB, 128>>>(qkv, att);
        sgemm_nn_splitk<<<dim3(D_ / 128, T_ / 128, NSPLIT), 256>>>(
            T_, D_, D_, D_ / NSPLIT, att, wo, part);
        reduce3_kernel<<<redBlocks, 256>>>(part, bol, h);
        ln_kernel<<<T_, 256>>>(h, ln2g + l * D_, ln2b + l * D_, a);
        sgemm_nn<<<dim3(DFF_ / 128, T_ / 128), 256>>>(
            T_, DFF_, D_, a, w1, b1l, nullptr, ff, 1);
        sgemm_nn_splitk<<<dim3(D_ / 128, T_ / 128, NSPLIT), 256>>>(
            T_, D_, DFF_, DFF_ / NSPLIT, ff, w2, part);
        reduce3_kernel<<<redBlocks, 256>>>(part, b2l, h);
    }

    ln_kernel<<<T_, 256>>>(h, lnfg, lnfb, a);
    sgemm_nt<<<dim3((V_ + 127) / 128, T_ / 128), 256>>>(
        T_, V_, D_, a, Wlm, out);
}